// round 7
// baseline (speedup 1.0000x reference)
#include <cuda_runtime.h>
#include <cuda_bf16.h>
#include <cstdint>

#define HH 8
#define DD 512
#define BB 128
#define SS 2048
#define EE 4096   // HH*DD
#define KSPLIT 4

// Scratch (no allocations allowed)
__device__ float g_q[BB * EE];             // projected, pre-scaled query
__device__ float g_sc[BB * SS * HH];       // masked scores / probabilities (8MB)
__device__ float g_xp[2 * BB * EE];        // attention output partials (2 halves)
__device__ float g_part[KSPLIT * BB * EE]; // k-split GEMM partials

// Single dynamic-smem symbol for the whole TU
extern __shared__ char dyn_smem[];

__device__ __forceinline__ void fma4(float4& a, float p, float4 v) {
    a.x += p * v.x; a.y += p * v.y; a.z += p * v.z; a.w += p * v.w;
}

// m16n8k16 row.col bf16 mma, fp32 accumulate (standard PTX, sm_80+)
__device__ __forceinline__ void mma16816(float* c, const uint32_t* a, const uint32_t* b) {
    asm volatile(
        "mma.sync.aligned.m16n8k16.row.col.f32.bf16.bf16.f32 "
        "{%0,%1,%2,%3}, {%4,%5,%6,%7}, {%8,%9}, {%0,%1,%2,%3};"
        : "+f"(c[0]), "+f"(c[1]), "+f"(c[2]), "+f"(c[3])
        : "r"(a[0]), "r"(a[1]), "r"(a[2]), "r"(a[3]), "r"(b[0]), "r"(b[1]));
}

// pack float2 -> bf16x2 (hi) and residual (lo)
__device__ __forceinline__ uint32_t bfhi(float2 v) {
    __nv_bfloat162 h = __floats2bfloat162_rn(v.x, v.y);
    return *(uint32_t*)&h;
}
__device__ __forceinline__ uint32_t bflo(float2 v, uint32_t hbits) {
    __nv_bfloat162 h = *(__nv_bfloat162*)&hbits;
    float2 f = __bfloat1622float2(h);
    __nv_bfloat162 l = __floats2bfloat162_rn(v.x - f.x, v.y - f.y);
    return *(uint32_t*)&l;
}

// ===========================================================================
// gemm_part<K, KCHUNK, SUMX>: part[p] = X[128,K_range] @ W[4096,K_range]^T
// BM=128, BN=64 -> grid (64, KSPLIT) = 256 CTAs, 2 CTAs/SM.
// Register-prefetch pipeline: LDG chunk c+1 overlaps MMA on chunk c.
// If SUMX, X element i = X[i] + X2[i] (folds attention partial reduce).
// ===========================================================================
#define KSTEP 32
#define SW 20                     // words per row in smem
#define ARR_A (128 * SW)          // 2560 words
#define ARR_B (64 * SW)           // 1280 words
#define BUFW (2 * ARR_A + 2 * ARR_B)  // 7680 words per buffer
#define GEMM_SMEM (2 * BUFW * 4)  // 61440 bytes

template <int K, int KCHUNK, bool SUMX>
__global__ void __launch_bounds__(256, 2)
gemm_part(const float* __restrict__ X, const float* __restrict__ X2,
          const float* __restrict__ W, float* __restrict__ part) {
    uint32_t* sw = (uint32_t*)dyn_smem;
    const int tid = threadIdx.x;
    const int wid = tid >> 5;
    const int lane = tid & 31;
    const int g = lane >> 2;          // 0..7
    const int tg = lane & 3;          // 0..3
    const int wm = wid >> 2;          // 0..1: M half (64 rows)
    const int wn = wid & 3;           // 0..3: N quarter (16 cols)
    const int fbase = blockIdx.x * 64;
    const int p = blockIdx.y;
    const int kbeg = p * KCHUNK;

    const int lrow = tid >> 3;        // 0..31 step: loader row base
    const int lq4 = tid & 7;

    float acc[4][2][4];
    #pragma unroll
    for (int mi = 0; mi < 4; mi++)
        #pragma unroll
        for (int ni = 0; ni < 2; ni++)
            #pragma unroll
            for (int r = 0; r < 4; r++) acc[mi][ni][r] = 0.0f;

    const int NC = KCHUNK / KSTEP;
    float4 pa[4], pb[2];

    // ---- prefetch + store chunk 0 ----
    #pragma unroll
    for (int i = 0; i < 4; i++) {
        const int row = lrow + i * 32;
        const float* xp = X + (size_t)row * K + kbeg + lq4 * 4;
        pa[i] = *(const float4*)xp;
        if (SUMX) {
            float4 v2 = *(const float4*)(X2 + (size_t)row * K + kbeg + lq4 * 4);
            pa[i].x += v2.x; pa[i].y += v2.y; pa[i].z += v2.z; pa[i].w += v2.w;
        }
    }
    #pragma unroll
    for (int i = 0; i < 2; i++) {
        const int row = lrow + i * 32;
        pb[i] = *(const float4*)(W + (size_t)(fbase + row) * K + kbeg + lq4 * 4);
    }
    {
        uint32_t* Ah = sw;
        uint32_t* Al = Ah + ARR_A;
        uint32_t* Bh = Al + ARR_A;
        uint32_t* Bl = Bh + ARR_B;
        const int off = lrow * SW + lq4 * 2;
        #pragma unroll
        for (int i = 0; i < 4; i++) {
            uint32_t h01 = bfhi(make_float2(pa[i].x, pa[i].y));
            uint32_t h23 = bfhi(make_float2(pa[i].z, pa[i].w));
            uint32_t l01 = bflo(make_float2(pa[i].x, pa[i].y), h01);
            uint32_t l23 = bflo(make_float2(pa[i].z, pa[i].w), h23);
            *(uint2*)(Ah + off + i * 32 * SW) = make_uint2(h01, h23);
            *(uint2*)(Al + off + i * 32 * SW) = make_uint2(l01, l23);
        }
        #pragma unroll
        for (int i = 0; i < 2; i++) {
            uint32_t h01 = bfhi(make_float2(pb[i].x, pb[i].y));
            uint32_t h23 = bfhi(make_float2(pb[i].z, pb[i].w));
            uint32_t l01 = bflo(make_float2(pb[i].x, pb[i].y), h01);
            uint32_t l23 = bflo(make_float2(pb[i].z, pb[i].w), h23);
            *(uint2*)(Bh + off + i * 32 * SW) = make_uint2(h01, h23);
            *(uint2*)(Bl + off + i * 32 * SW) = make_uint2(l01, l23);
        }
    }
    __syncthreads();

    for (int c = 0; c < NC; c++) {
        const int q = c & 1;
        // ---- issue LDGs for chunk c+1 (overlap with compute below) ----
        if (c + 1 < NC) {
            const int k0 = kbeg + (c + 1) * KSTEP;
            #pragma unroll
            for (int i = 0; i < 4; i++) {
                const int row = lrow + i * 32;
                pa[i] = *(const float4*)(X + (size_t)row * K + k0 + lq4 * 4);
                if (SUMX) {
                    float4 v2 = *(const float4*)(X2 + (size_t)row * K + k0 + lq4 * 4);
                    pa[i].x += v2.x; pa[i].y += v2.y; pa[i].z += v2.z; pa[i].w += v2.w;
                }
            }
            #pragma unroll
            for (int i = 0; i < 2; i++) {
                const int row = lrow + i * 32;
                pb[i] = *(const float4*)(W + (size_t)(fbase + row) * K + k0 + lq4 * 4);
            }
        }

        // ---- compute on buffer q ----
        uint32_t* Ah = sw + q * BUFW;
        uint32_t* Al = Ah + ARR_A;
        uint32_t* Bh = Al + ARR_A;
        uint32_t* Bl = Bh + ARR_B;
        #pragma unroll
        for (int sub = 0; sub < 2; sub++) {
            const int wb = sub * 8 + tg;
            uint32_t bh[2][2], bl[2][2];
            #pragma unroll
            for (int ni = 0; ni < 2; ni++) {
                const int r = wn * 16 + ni * 8 + g;
                bh[ni][0] = Bh[r * SW + wb];
                bh[ni][1] = Bh[r * SW + wb + 4];
                bl[ni][0] = Bl[r * SW + wb];
                bl[ni][1] = Bl[r * SW + wb + 4];
            }
            #pragma unroll
            for (int mi = 0; mi < 4; mi++) {
                const int r0 = wm * 64 + mi * 16 + g;
                const int r1 = r0 + 8;
                uint32_t ah[4], al[4];
                ah[0] = Ah[r0 * SW + wb];
                ah[1] = Ah[r1 * SW + wb];
                ah[2] = Ah[r0 * SW + wb + 4];
                ah[3] = Ah[r1 * SW + wb + 4];
                al[0] = Al[r0 * SW + wb];
                al[1] = Al[r1 * SW + wb];
                al[2] = Al[r0 * SW + wb + 4];
                al[3] = Al[r1 * SW + wb + 4];
                #pragma unroll
                for (int ni = 0; ni < 2; ni++) {
                    mma16816(acc[mi][ni], ah, bh[ni]);
                    mma16816(acc[mi][ni], al, bh[ni]);
                    mma16816(acc[mi][ni], ah, bl[ni]);
                }
            }
        }

        // ---- convert + store chunk c+1 into the other buffer ----
        if (c + 1 < NC) {
            uint32_t* Ah2 = sw + ((c + 1) & 1) * BUFW;
            uint32_t* Al2 = Ah2 + ARR_A;
            uint32_t* Bh2 = Al2 + ARR_A;
            uint32_t* Bl2 = Bh2 + ARR_B;
            const int off = lrow * SW + lq4 * 2;
            #pragma unroll
            for (int i = 0; i < 4; i++) {
                uint32_t h01 = bfhi(make_float2(pa[i].x, pa[i].y));
                uint32_t h23 = bfhi(make_float2(pa[i].z, pa[i].w));
                uint32_t l01 = bflo(make_float2(pa[i].x, pa[i].y), h01);
                uint32_t l23 = bflo(make_float2(pa[i].z, pa[i].w), h23);
                *(uint2*)(Ah2 + off + i * 32 * SW) = make_uint2(h01, h23);
                *(uint2*)(Al2 + off + i * 32 * SW) = make_uint2(l01, l23);
            }
            #pragma unroll
            for (int i = 0; i < 2; i++) {
                uint32_t h01 = bfhi(make_float2(pb[i].x, pb[i].y));
                uint32_t h23 = bfhi(make_float2(pb[i].z, pb[i].w));
                uint32_t l01 = bflo(make_float2(pb[i].x, pb[i].y), h01);
                uint32_t l23 = bflo(make_float2(pb[i].z, pb[i].w), h23);
                *(uint2*)(Bh2 + off + i * 32 * SW) = make_uint2(h01, h23);
                *(uint2*)(Bl2 + off + i * 32 * SW) = make_uint2(l01, l23);
            }
        }
        __syncthreads();
    }

    float* pp = part + (size_t)p * BB * EE;
    #pragma unroll
    for (int mi = 0; mi < 4; mi++) {
        const int m0 = wm * 64 + mi * 16 + g;
        #pragma unroll
        for (int ni = 0; ni < 2; ni++) {
            const int col = fbase + wn * 16 + ni * 8 + tg * 2;
            *(float2*)(pp + (size_t)m0 * EE + col)       = make_float2(acc[mi][ni][0], acc[mi][ni][1]);
            *(float2*)(pp + (size_t)(m0 + 8) * EE + col) = make_float2(acc[mi][ni][2], acc[mi][ni][3]);
        }
    }
}

// out = (sum_p part[p] + bias) * scale
__global__ void __launch_bounds__(256) reduce_part(const float* __restrict__ bias,
                                                   float* __restrict__ out, float scale) {
    const int t = blockIdx.x * 256 + threadIdx.x;
    const int base = t * 4;
    const int col = base & (EE - 1);
    float4 a = *(const float4*)(g_part + base);
    float4 b = *(const float4*)(g_part + 1 * BB * EE + base);
    float4 c = *(const float4*)(g_part + 2 * BB * EE + base);
    float4 d = *(const float4*)(g_part + 3 * BB * EE + base);
    float4 bi = *(const float4*)(bias + col);
    float4 o;
    o.x = (a.x + b.x + c.x + d.x + bi.x) * scale;
    o.y = (a.y + b.y + c.y + d.y + bi.y) * scale;
    o.z = (a.z + b.z + c.z + d.z + bi.z) * scale;
    o.w = (a.w + b.w + c.w + d.w + bi.w) * scale;
    *(float4*)(out + base) = o;
}

// ---------------------------------------------------------------------------
// B1: scores. grid (2, BB): blockIdx.x = s-half, blockIdx.y = batch.
// 256 threads = 8 warps, each warp 8 m-tiles of 16 s. mma bf16 hi/lo split.
// smem: qbA/qbB frag tables (16KB).
// ---------------------------------------------------------------------------
__global__ void __launch_bounds__(256, 1) score_kernel(const float* __restrict__ key,
                                                       const int* __restrict__ mask) {
    uint2* qbA = (uint2*)dyn_smem;                  // [32 ks][32 lane]
    uint2* qbB = (uint2*)(dyn_smem + 8192);

    const int half = blockIdx.x;
    const int b = blockIdx.y;
    const int tid = threadIdx.x;
    const int warp = tid >> 5;
    const int lane = tid & 31;
    const int gid = lane >> 2;
    const int tg = lane & 3;

    // build q B-frag tables (hi/lo). entry (ks, L): h=L>>2, d0=ks*16+(L&3)*2
    for (int idx = tid; idx < 1024; idx += 256) {
        const int ks = idx >> 5, L = idx & 31;
        const int h = L >> 2, d0 = ks * 16 + (L & 3) * 2;
        const float* qp = g_q + (size_t)b * EE + h * DD + d0;
        float2 v0 = make_float2(qp[0], qp[1]);
        float2 v1 = make_float2(qp[8], qp[9]);
        uint32_t h0 = bfhi(v0), l0 = bflo(v0, h0);
        uint32_t h1 = bfhi(v1), l1 = bflo(v1, h1);
        qbA[idx] = make_uint2(h0, h1);
        qbB[idx] = make_uint2(l0, l1);
    }
    __syncthreads();

    const float* Kb = key + (size_t)b * SS * DD;
    const int*   Mb = mask + (size_t)b * SS;
    float* scb = g_sc + (size_t)b * SS * HH;

    for (int i = 0; i < 8; i++) {
        const int mt = half * 64 + warp * 8 + i;
        const int s0 = mt * 16 + gid;
        const float* K0 = Kb + (size_t)s0 * DD + tg * 2;
        float c[4] = {0.0f, 0.0f, 0.0f, 0.0f};
        #pragma unroll 4
        for (int ks = 0; ks < 32; ks++) {
            const float* kp = K0 + ks * 16;
            float2 va0 = *(const float2*)(kp);
            float2 va1 = *(const float2*)(kp + 8 * DD);
            float2 va2 = *(const float2*)(kp + 8);
            float2 va3 = *(const float2*)(kp + 8 * DD + 8);
            uint32_t ah[4], al[4];
            ah[0] = bfhi(va0); al[0] = bflo(va0, ah[0]);
            ah[1] = bfhi(va1); al[1] = bflo(va1, ah[1]);
            ah[2] = bfhi(va2); al[2] = bflo(va2, ah[2]);
            ah[3] = bfhi(va3); al[3] = bflo(va3, ah[3]);
            uint2 bh = qbA[ks * 32 + lane];
            uint2 bl = qbB[ks * 32 + lane];
            mma16816(c, ah, (const uint32_t*)&bh);
            mma16816(c, al, (const uint32_t*)&bh);
            mma16816(c, ah, (const uint32_t*)&bl);
        }
        const int s1 = s0 + 8, h0 = tg * 2;
        const int m0 = Mb[s0], m1 = Mb[s1];
        scb[s0 * 8 + h0]     = m0 ? c[0] : -1e9f;
        scb[s0 * 8 + h0 + 1] = m0 ? c[1] : -1e9f;
        scb[s1 * 8 + h0]     = m1 ? c[2] : -1e9f;
        scb[s1 * 8 + h0 + 1] = m1 ? c[3] : -1e9f;
    }
}

// ---------------------------------------------------------------------------
// B2: softmax. grid BB, 256 threads. Stage scores in smem (64KB), softmax
// per head (warp h), write probabilities back.
// ---------------------------------------------------------------------------
__global__ void __launch_bounds__(256, 1) softmax_kernel() {
    float* sc = (float*)dyn_smem;  // 16384 floats
    const int b = blockIdx.x;
    const int tid = threadIdx.x;
    const int warp = tid >> 5;
    const int lane = tid & 31;
    float* scb = g_sc + (size_t)b * SS * HH;

    #pragma unroll
    for (int i = 0; i < 16; i++)
        ((float4*)sc)[tid + i * 256] = ((const float4*)scb)[tid + i * 256];
    __syncthreads();

    {
        float m = -3.0e38f;
        for (int i = lane; i < SS; i += 32) m = fmaxf(m, sc[i * 8 + warp]);
        #pragma unroll
        for (int off = 16; off; off >>= 1)
            m = fmaxf(m, __shfl_xor_sync(0xffffffffu, m, off));
        float sum = 0.0f;
        for (int i = lane; i < SS; i += 32) {
            float ev = __expf(sc[i * 8 + warp] - m);
            sc[i * 8 + warp] = ev;
            sum += ev;
        }
        #pragma unroll
        for (int off = 16; off; off >>= 1)
            sum += __shfl_xor_sync(0xffffffffu, sum, off);
        const float inv = 1.0f / sum;
        for (int i = lane; i < SS; i += 32) sc[i * 8 + warp] *= inv;
    }
    __syncthreads();

    #pragma unroll
    for (int i = 0; i < 16; i++)
        ((float4*)scb)[tid + i * 256] = ((const float4*)sc)[tid + i * 256];
}

// ---------------------------------------------------------------------------
// B3: x_partial[half] = P[half] @ V[half]. grid (2, BB), 512 threads.
// Stage probs (32KB smem), 4 s-subgroups x 128 threads, thread: 4 d, 8 heads.
// ---------------------------------------------------------------------------
__global__ void __launch_bounds__(512, 1) pv_kernel(const float* __restrict__ value) {
    float* sc = (float*)dyn_smem;  // 8192 floats (this half's probs)
    const int half = blockIdx.x;
    const int b = blockIdx.y;
    const int tid = threadIdx.x;

    const float* scb = g_sc + (size_t)b * SS * HH + half * 8192;
    #pragma unroll
    for (int i = 0; i < 4; i++)
        ((float4*)sc)[tid + i * 512] = ((const float4*)scb)[tid + i * 512];
    __syncthreads();

    const int d4 = (tid & 127) * 4;
    const int sg = tid >> 7;             // 0..3
    const float* Vb = value + (size_t)b * SS * DD + (size_t)half * 1024 * DD;

    float4 a0 = {0,0,0,0}, a1 = a0, a2 = a0, a3 = a0, a4 = a0, a5 = a0, a6 = a0, a7 = a0;
    const int s_beg = sg * 256;
    #pragma unroll 2
    for (int s = s_beg; s < s_beg + 256; s += 2) {
        float4 v0 = *(const float4*)(Vb + (size_t)s * DD + d4);
        float4 v1 = *(const float4*)(Vb + (size_t)(s + 1) * DD + d4);
        float4 p0 = *(const float4*)(sc + s * 8);
        float4 p1 = *(const float4*)(sc + s * 8 + 4);
        float4 p2 = *(const float4*)(sc + (s + 1) * 8);
        float4 p3 = *(const float4*)(sc + (s + 1) * 8 + 4);
        fma4(a0, p0.x, v0); fma4(a1, p0.y, v0); fma4(a2, p0.z, v0); fma4(a3, p0.w, v0);
        fma4(a4, p1.x, v0); fma4(a5, p1.y, v0); fma4(a6, p1.z, v0); fma4(a7, p1.w, v0);
        fma4(a0, p2.x, v1); fma4(a1, p2.y, v1); fma4(a2, p2.z, v1); fma4(a3, p2.w, v1);
        fma4(a4, p3.x, v1); fma4(a5, p3.y, v1); fma4(a6, p3.z, v1); fma4(a7, p3.w, v1);
    }
    __syncthreads();  // everyone done reading sc (reuse as scratch below)

    // combine 4 s-subgroups: 0,1 write; 2,3 add; final sum of 2 buffers
    if (sg < 2) {
        float* dst = sc + sg * 4096;
        *(float4*)(dst + 0 * DD + d4) = a0;
        *(float4*)(dst + 1 * DD + d4) = a1;
        *(float4*)(dst + 2 * DD + d4) = a2;
        *(float4*)(dst + 3 * DD + d4) = a3;
        *(float4*)(dst + 4 * DD + d4) = a4;
        *(float4*)(dst + 5 * DD + d4) = a5;
        *(float4*)(dst + 6 * DD + d4) = a6;
        *(float4*)(dst + 7 * DD + d4) = a7;
    }
    __syncthreads();
    if (sg >= 2) {
        float* dst = sc + (sg - 2) * 4096;
        float4* p;
        p = (float4*)(dst + 0 * DD + d4); p->x += a0.x; p->y += a0.y; p->z += a0.z; p->w += a0.w;
        p = (float4*)(dst + 1 * DD + d4); p->x += a1.x; p->y += a1.y; p->z += a1.z; p->w += a1.w;
        p = (float4*)(dst + 2 * DD + d4); p->x += a2.x; p->y += a2.y; p->z += a2.z; p->w += a2.w;
        p = (float4*)(dst + 3 * DD + d4); p->x += a3.x; p->y += a3.y; p->z += a3.z; p->w += a3.w;
        p = (float4*)(dst + 4 * DD + d4); p->x += a4.x; p->y += a4.y; p->z += a4.z; p->w += a4.w;
        p = (float4*)(dst + 5 * DD + d4); p->x += a5.x; p->y += a5.y; p->z += a5.z; p->w += a5.w;
        p = (float4*)(dst + 6 * DD + d4); p->x += a6.x; p->y += a6.y; p->z += a6.z; p->w += a6.w;
        p = (float4*)(dst + 7 * DD + d4); p->x += a7.x; p->y += a7.y; p->z += a7.z; p->w += a7.w;
    }
    __syncthreads();

    const int idx = tid * 8;
    float4 u0 = *(float4*)(sc + idx);
    float4 u1 = *(float4*)(sc + idx + 4);
    float4 w0 = *(float4*)(sc + 4096 + idx);
    float4 w1 = *(float4*)(sc + 4096 + idx + 4);
    float4 r0, r1;
    r0.x = u0.x + w0.x; r0.y = u0.y + w0.y; r0.z = u0.z + w0.z; r0.w = u0.w + w0.w;
    r1.x = u1.x + w1.x; r1.y = u1.y + w1.y; r1.z = u1.z + w1.z; r1.w = u1.w + w1.w;
    float* xp = g_xp + (size_t)half * BB * EE + (size_t)b * EE;
    *(float4*)(xp + idx)     = r0;
    *(float4*)(xp + idx + 4) = r1;
}

// ---------------------------------------------------------------------------
extern "C" void kernel_launch(void* const* d_in, const int* in_sizes, int n_in,
                              void* d_out, int out_size) {
    const float* query = (const float*)d_in[0];
    const float* key   = (const float*)d_in[1];
    const float* value = (const float*)d_in[2];
    const int*   mask  = (const int*)d_in[3];
    const float* W_in  = (const float*)d_in[4];
    const float* b_in  = (const float*)d_in[5];
    const float* W_out = (const float*)d_in[6];
    const float* b_out = (const float*)d_in[7];
    float* out = (float*)d_out;

    cudaFuncSetAttribute(gemm_part<512, 128, false>,  cudaFuncAttributeMaxDynamicSharedMemorySize, GEMM_SMEM);
    cudaFuncSetAttribute(gemm_part<4096, 1024, true>, cudaFuncAttributeMaxDynamicSharedMemorySize, GEMM_SMEM);
    cudaFuncSetAttribute(softmax_kernel, cudaFuncAttributeMaxDynamicSharedMemorySize, 65536);

    float* gq; cudaGetSymbolAddress((void**)&gq, g_q);
    float* gxp; cudaGetSymbolAddress((void**)&gxp, g_xp);
    float* gp; cudaGetSymbolAddress((void**)&gp, g_part);

    dim3 ggrid(EE / 64, KSPLIT);   // 256 CTAs
    dim3 agrid(2, BB);             // 256 CTAs

    gemm_part<512, 128, false><<<ggrid, 256, GEMM_SMEM>>>(query, nullptr, W_in, gp);
    reduce_part<<<BB * EE / 1024, 256>>>(b_in, gq, 0.04419417382415922f);
    score_kernel<<<agrid, 256, 16384>>>(key, mask);
    softmax_kernel<<<BB, 256, 65536>>>();
    pv_kernel<<<agrid, 512, 32768>>>(value);
    gemm_part<4096, 1024, true><<<ggrid, 256, GEMM_SMEM>>>(gxp, gxp + BB * EE, W_out, gp);
    reduce_part<<<BB * EE / 1024, 256>>>(b_out, out, 1.0f);
}